// round 5
// baseline (speedup 1.0000x reference)
#include <cuda_runtime.h>
#include <math_constants.h>

// Roi_61564061221098 round 5: smem-staged RoI max pooling.
// grid = 4 images x 256 channel-pairs. Each block loads its two (50x68) f32
// planes ONCE into smem (interleaved float2), then pools every roi of that
// image from shared memory. Prep kernel builds packed per-roi geometry
// (XLA-exact: x/7 computed as x * fl(1/7)) and per-image roi lists.

#define NC    512
#define FH    50
#define FW    68
#define PLANE (FH * FW)
#define PP    7
#define SCALE 0.0625f
#define NEG_INF (-CUDART_INF_F)
#define MAXR  4096

// packed per-roi record: [0]=w0, [1]=span, [2]=maxw,
// [3..9] = hs | he<<8 | (ws-w0)<<16 | (we-w0)<<24
__device__ __align__(16) int g_rec[MAXR * 16];
__device__ int g_list[4 * MAXR];
__device__ int g_cnt[4];

__global__ void roi_prep(const float* __restrict__ rois,
                         const int*   __restrict__ ridx, int R)
{
    const int tid = threadIdx.x;
    if (tid < 4) g_cnt[tid] = 0;
    __syncthreads();

    for (int r = tid; r < R; r += blockDim.x) {
        const float y1 = rois[r * 4 + 0];
        const float x1 = rois[r * 4 + 1];
        const float y2 = rois[r * 4 + 2];
        const float x2 = rois[r * 4 + 3];
        const float rb0 = rintf(__fmul_rn(x1, SCALE));
        const float rb1 = rintf(__fmul_rn(y1, SCALE));
        const float rb2 = rintf(__fmul_rn(x2, SCALE));
        const float rb3 = rintf(__fmul_rn(y2, SCALE));
        const float roiw = fmaxf(__fadd_rn(__fsub_rn(rb2, rb0), 1.0f), 1.0f);
        const float roih = fmaxf(__fadd_rn(__fsub_rn(rb3, rb1), 1.0f), 1.0f);
        const float R7 = (float)(1.0 / 7.0);      // XLA: x/7 -> x * fl(1/7)
        const float bw = __fmul_rn(roiw, R7);
        const float bh = __fmul_rn(roih, R7);

        const int w0 = (int)fminf(fmaxf(rb0, 0.0f), (float)FW);   // == ws[0]
        int maxw = 0;
        int pack[PP];
#pragma unroll
        for (int p = 0; p < PP; p++) {
            const float fp  = (float)p;
            const float fp1 = (float)(p + 1);
            int hs = (int)fminf(fmaxf(__fadd_rn(floorf(__fmul_rn(fp,  bh)), rb1), 0.0f), (float)FH);
            int he = (int)fminf(fmaxf(__fadd_rn(ceilf (__fmul_rn(fp1, bh)), rb1), 0.0f), (float)FH);
            int ws = (int)fminf(fmaxf(__fadd_rn(floorf(__fmul_rn(fp,  bw)), rb0), 0.0f), (float)FW);
            int we = (int)fminf(fmaxf(__fadd_rn(ceilf (__fmul_rn(fp1, bw)), rb0), 0.0f), (float)FW);
            maxw = max(maxw, we - ws);
            pack[p] = hs | (he << 8) | ((ws - w0) << 16) | ((we - w0) << 24);
        }
        int* rec = g_rec + r * 16;
        rec[0] = w0;
        rec[1] = (pack[PP - 1] >> 24) & 0xff;   // span = we[6]-w0
        rec[2] = maxw;
#pragma unroll
        for (int p = 0; p < PP; p++) rec[3 + p] = pack[p];

        const int n = ridx[r];
        const int pos = atomicAdd(&g_cnt[n], 1);
        if (pos < MAXR) g_list[n * MAXR + pos] = r;
    }
}

template <int NR>
__device__ __forceinline__ void pool_roi(const float2* __restrict__ sp,
                                         float2* __restrict__ scol,
                                         float2* __restrict__ sout,
                                         int v, int w0, int maxw, int lane,
                                         int j0, int j1)
{
#pragma unroll
    for (int ph = 0; ph < PP; ph++) {
        const int pk = __shfl_sync(0xffffffffu, v, 3 + ph);
        const int h0 = pk & 0xff;
        const int h1 = (pk >> 8) & 0xff;

        float2 m[NR];
#pragma unroll
        for (int q = 0; q < NR; q++) m[q] = make_float2(NEG_INF, NEG_INF);

        const float2* p = sp + h0 * FW + w0 + lane;
        for (int h = h0; h < h1; h++, p += FW) {
#pragma unroll
            for (int q = 0; q < NR; q++) {      // unguarded: smem padded,
                const float2 t = p[q * 32];     // cols >= span never consumed
                m[q].x = fmaxf(m[q].x, t.x);
                m[q].y = fmaxf(m[q].y, t.y);
            }
        }
#pragma unroll
        for (int q = 0; q < NR; q++) scol[q * 32 + lane] = m[q];
        __syncwarp();
        if (lane < PP) {
            float2 mm = make_float2(NEG_INF, NEG_INF);
            for (int k = 0; k < maxw; k++) {
                const int j = j0 + k;
                if (j < j1) {
                    const float2 t = scol[j];
                    mm.x = fmaxf(mm.x, t.x);
                    mm.y = fmaxf(mm.y, t.y);
                }
            }
            sout[ph * PP + lane] = make_float2(mm.x == NEG_INF ? 0.0f : mm.x,
                                               mm.y == NEG_INF ? 0.0f : mm.y);
        }
        __syncwarp();
    }
}

__global__ __launch_bounds__(256, 6)
void roi_pool(const float* __restrict__ x, float* __restrict__ out)
{
    __shared__ float2 s_plane[PLANE + 104];   // pad: unguarded reads stay in-bounds
    __shared__ float2 s_col[8][96];
    __shared__ float2 s_out[8][52];

    const int n    = blockIdx.x >> 8;
    const int cp   = blockIdx.x & 255;        // channel pair: c0 = 2*cp
    const int tid  = threadIdx.x;
    const int warp = tid >> 5;
    const int lane = tid & 31;

    // stage both planes (interleaved) — read each input element exactly once
    const float* __restrict__ p0 = x + ((n * NC + cp * 2) * PLANE);
    for (int i = tid; i < PLANE; i += 256)
        s_plane[i] = make_float2(__ldg(p0 + i), __ldg(p0 + PLANE + i));
    __syncthreads();

    const int cnt = g_cnt[n];
    const int* __restrict__ lst = g_list + n * MAXR;

    for (int i = warp; i < cnt; i += 8) {
        const int r = lst[i];
        int v = 0;
        if (lane < 16) v = g_rec[r * 16 + lane];
        const int w0   = __shfl_sync(0xffffffffu, v, 0);
        const int span = __shfl_sync(0xffffffffu, v, 1);
        const int maxw = __shfl_sync(0xffffffffu, v, 2);
        const int mypk = __shfl_sync(0xffffffffu, v, 3 + (lane < PP ? lane : 0));
        const int j0 = (mypk >> 16) & 0xff;
        const int j1 = (mypk >> 24) & 0xff;

        if (span <= 32)
            pool_roi<1>(s_plane, s_col[warp], s_out[warp], v, w0, maxw, lane, j0, j1);
        else if (span <= 64)
            pool_roi<2>(s_plane, s_col[warp], s_out[warp], v, w0, maxw, lane, j0, j1);
        else
            pool_roi<3>(s_plane, s_col[warp], s_out[warp], v, w0, maxw, lane, j0, j1);

        // write 2 x 49 contiguous floats
        const int ob = r * (NC * PP * PP) + cp * 2 * (PP * PP);
        const float2 t = s_out[warp][lane];
        out[ob + lane]      = t.x;
        out[ob + 49 + lane] = t.y;
        if (lane < 17) {
            const float2 u = s_out[warp][32 + lane];
            out[ob + 32 + lane] = u.x;
            out[ob + 81 + lane] = u.y;
        }
        __syncwarp();
    }
}

extern "C" void kernel_launch(void* const* d_in, const int* in_sizes, int n_in,
                              void* d_out, int out_size)
{
    const float* x    = (const float*)d_in[0];
    const float* rois = (const float*)d_in[1];
    const int*   ridx = (const int*)d_in[2];
    float*       out  = (float*)d_out;
    const int R = in_sizes[2];

    roi_prep<<<1, 256>>>(rois, ridx, R);
    roi_pool<<<4 * 256, 256>>>(x, out);
}

// round 6
// speedup vs baseline: 2.2543x; 2.2543x over previous
#include <cuda_runtime.h>
#include <math_constants.h>

// Roi_61564061221098 round 6: R4 design (warp = roi x 4 channels, LDG from L2)
// + h-bin boundary-row dedupe (carry last row in regs) + single-syncwarp
// ping-pong column buffer.

#define NC    512
#define FH    50
#define FW    68
#define PLANE (FH * FW)
#define PP    7
#define SCALE 0.0625f
#define NEG_INF (-CUDART_INF_F)

// packed per-roi record: [0]=base(n*NC*PLANE + w0), [1]=span, [2]=maxw,
// [3..9] = hs | he<<8 | (ws-w0)<<16 | (we-w0)<<24
__device__ __align__(16) int g_rec[4096 * 16];

__global__ void roi_prep(const float* __restrict__ rois,
                         const int*   __restrict__ ridx, int R)
{
    int r = blockIdx.x * blockDim.x + threadIdx.x;
    if (r >= R) return;

    const float y1 = rois[r * 4 + 0];
    const float x1 = rois[r * 4 + 1];
    const float y2 = rois[r * 4 + 2];
    const float x2 = rois[r * 4 + 3];
    const float rb0 = rintf(__fmul_rn(x1, SCALE));
    const float rb1 = rintf(__fmul_rn(y1, SCALE));
    const float rb2 = rintf(__fmul_rn(x2, SCALE));
    const float rb3 = rintf(__fmul_rn(y2, SCALE));
    const float roiw = fmaxf(__fadd_rn(__fsub_rn(rb2, rb0), 1.0f), 1.0f);
    const float roih = fmaxf(__fadd_rn(__fsub_rn(rb3, rb1), 1.0f), 1.0f);
    const float R7 = (float)(1.0 / 7.0);          // XLA: x/7 -> x * fl(1/7)
    const float bw = __fmul_rn(roiw, R7);
    const float bh = __fmul_rn(roih, R7);

    const int w0 = (int)fminf(fmaxf(rb0, 0.0f), (float)FW);   // == ws[0]
    int maxw = 0;
    int pack[PP];
#pragma unroll
    for (int p = 0; p < PP; p++) {
        const float fp  = (float)p;
        const float fp1 = (float)(p + 1);
        int hs = (int)fminf(fmaxf(__fadd_rn(floorf(__fmul_rn(fp,  bh)), rb1), 0.0f), (float)FH);
        int he = (int)fminf(fmaxf(__fadd_rn(ceilf (__fmul_rn(fp1, bh)), rb1), 0.0f), (float)FH);
        int ws = (int)fminf(fmaxf(__fadd_rn(floorf(__fmul_rn(fp,  bw)), rb0), 0.0f), (float)FW);
        int we = (int)fminf(fmaxf(__fadd_rn(ceilf (__fmul_rn(fp1, bw)), rb0), 0.0f), (float)FW);
        maxw = max(maxw, we - ws);
        pack[p] = hs | (he << 8) | ((ws - w0) << 16) | ((we - w0) << 24);
    }
    int* rec = g_rec + r * 16;
    rec[0] = ridx[r] * (NC * PLANE) + w0;
    rec[1] = (pack[PP - 1] >> 24) & 0xff;
    rec[2] = maxw;
#pragma unroll
    for (int p = 0; p < PP; p++) rec[3 + p] = pack[p];
}

template <int NR>
__device__ __forceinline__ void pool_warp(const float* __restrict__ fm,
                                          int v, int span, int maxw, int lane,
                                          float* __restrict__ scol,
                                          float* __restrict__ sout)
{
    const int ch = lane >> 3;          // reduce-phase channel
    const int pw = lane & 7;           // reduce-phase pw bin
    const int mypk = __shfl_sync(0xffffffffu, v, 3 + (pw < PP ? pw : 0));
    const int j0 = (mypk >> 16) & 0xff;
    const int j1 = (mypk >> 24) & 0xff;

    bool act[NR];
#pragma unroll
    for (int q = 0; q < NR; q++) act[q] = (lane + q * 32) < span;

    float t[NR][4];        // last row read (dedupe carry)
    int lasth = -2;

#pragma unroll
    for (int ph = 0; ph < PP; ph++) {
        const int pk = __shfl_sync(0xffffffffu, v, 3 + ph);
        const int h0 = pk & 0xff;
        const int h1 = (pk >> 8) & 0xff;

        float m[NR][4];
        int hstart = h0;
        if (lasth == h0 && h0 < h1) {       // boundary row already in regs
#pragma unroll
            for (int q = 0; q < NR; q++)
#pragma unroll
                for (int k = 0; k < 4; k++) m[q][k] = t[q][k];
            hstart = h0 + 1;
        } else {
#pragma unroll
            for (int q = 0; q < NR; q++)
#pragma unroll
                for (int k = 0; k < 4; k++) m[q][k] = NEG_INF;
        }

        const float* p = fm + hstart * FW;
        for (int h = hstart; h < h1; h++, p += FW) {
#pragma unroll
            for (int q = 0; q < NR; q++) {
                if (act[q]) {
#pragma unroll
                    for (int k = 0; k < 4; k++) {
                        t[q][k] = __ldg(p + lane + q * 32 + k * PLANE);
                        m[q][k] = fmaxf(m[q][k], t[q][k]);
                    }
                }
            }
        }
        if (h0 < h1) lasth = h1 - 1;        // t[] now holds row h1-1

        // ping-pong column buffer: one syncwarp per ph
        float* sc = scol + (ph & 1) * (4 * 97);
#pragma unroll
        for (int k = 0; k < 4; k++)
#pragma unroll
            for (int q = 0; q < NR; q++)
                sc[k * 97 + q * 32 + lane] = m[q][k];
        __syncwarp();

        // 4-channel-parallel per-pw reduce
        float mm = NEG_INF;
        const float* s = sc + ch * 97;
        for (int k2 = 0; k2 < maxw; k2++) {
            const int j = j0 + k2;
            if (j < j1) mm = fmaxf(mm, s[j]);
        }
        if (pw < PP)
            sout[ch * 49 + ph * PP + pw] = (mm == NEG_INF) ? 0.0f : mm;
    }
    __syncwarp();
}

__global__ __launch_bounds__(256, 6)
void roi_pool(const float* __restrict__ x, float* __restrict__ out, int R)
{
    __shared__ float s_col[8][2 * 4 * 97];
    __shared__ float s_out[8][200];

    const int r    = blockIdx.x;
    const int warp = threadIdx.x >> 5;
    const int lane = threadIdx.x & 31;
    const int c0   = blockIdx.y * 32 + warp * 4;   // 16 * 32 = 512 channels

    int v = 0;
    if (lane < 16) v = g_rec[r * 16 + lane];
    const int base = __shfl_sync(0xffffffffu, v, 0);
    const int span = __shfl_sync(0xffffffffu, v, 1);
    const int maxw = __shfl_sync(0xffffffffu, v, 2);

    const float* fm   = x + base + c0 * PLANE;     // row 0, col w0, channel c0
    float*       scol = s_col[warp];
    float*       sout = s_out[warp];

    if (span <= 32)      pool_warp<1>(fm, v, span, maxw, lane, scol, sout);
    else if (span <= 64) pool_warp<2>(fm, v, span, maxw, lane, scol, sout);
    else                 pool_warp<3>(fm, v, span, maxw, lane, scol, sout);

    // 196 contiguous floats per warp
    const long long ob = (long long)r * (NC * 49) + (long long)c0 * 49;
#pragma unroll
    for (int i = 0; i < 7; i++) {
        const int idx = i * 32 + lane;
        if (idx < 196) out[ob + idx] = sout[idx];
    }
}

extern "C" void kernel_launch(void* const* d_in, const int* in_sizes, int n_in,
                              void* d_out, int out_size)
{
    const float* x    = (const float*)d_in[0];
    const float* rois = (const float*)d_in[1];
    const int*   ridx = (const int*)d_in[2];
    float*       out  = (float*)d_out;
    const int R = in_sizes[2];

    roi_prep<<<(R + 255) / 256, 256>>>(rois, ridx, R);
    dim3 grid(R, NC / 32);
    roi_pool<<<grid, 256>>>(x, out, R);
}